// round 15
// baseline (speedup 1.0000x reference)
#include <cuda_runtime.h>
#include <cuda_fp16.h>
#include <cstdint>

#define TT 3072
#define DD 1024
#define NH 16
#define HX 64
#define LOG2E 1.4426950408889634f

// ---------------------------------------------------------------------------
// Global scratch (all single fp16).  Q is pre-scaled by log2(e).
// ---------------------------------------------------------------------------
__device__ __align__(16) __half g_xh[TT * DD];                    // x
__device__ __align__(16) __half g_wh[3 * DD * DD];                // W
__device__ __align__(16) __half g_qh[TT * DD];                    // [h][t][x] (x log2e)
__device__ __align__(16) __half g_kh[TT * DD];                    // [h][j][x]
__device__ __align__(16) __half g_vh[TT * DD];                    // [h][x][j]

// ---------------------------------------------------------------------------
// helpers
// ---------------------------------------------------------------------------
__device__ __forceinline__ uint32_t smem_u32(const void* p) {
    uint32_t a;
    asm("{ .reg .u64 t; cvta.to.shared.u64 t, %1; cvt.u32.u64 %0, t; }"
        : "=r"(a) : "l"(p));
    return a;
}
__device__ __forceinline__ void ldsm4(uint32_t& r0, uint32_t& r1,
                                      uint32_t& r2, uint32_t& r3, uint32_t a) {
    asm volatile("ldmatrix.sync.aligned.m8n8.x4.shared.b16 {%0,%1,%2,%3}, [%4];"
                 : "=r"(r0), "=r"(r1), "=r"(r2), "=r"(r3) : "r"(a));
}
__device__ __forceinline__ void mma16816h(float* c, const uint32_t* a,
                                          uint32_t b0, uint32_t b1) {
    asm volatile("mma.sync.aligned.m16n8k16.row.col.f32.f16.f16.f32 "
                 "{%0,%1,%2,%3}, {%4,%5,%6,%7}, {%8,%9}, {%0,%1,%2,%3};"
                 : "+f"(c[0]), "+f"(c[1]), "+f"(c[2]), "+f"(c[3])
                 : "r"(a[0]), "r"(a[1]), "r"(a[2]), "r"(a[3]), "r"(b0), "r"(b1));
}
__device__ __forceinline__ uint32_t pkh2(float a, float b) {
    __half2 t = __floats2half2_rn(a, b);
    return *(uint32_t*)&t;
}
__device__ __forceinline__ float ex2(float x) {
    float r;
    asm("ex2.approx.ftz.f32 %0, %1;" : "=f"(r) : "f"(x));
    return r;
}

#define CP16(dst, src) \
    asm volatile("cp.async.cg.shared.global [%0], [%1], 16;" \
                 :: "r"((uint32_t)(dst)), "l"((const void*)(src)) : "memory")
#define CPCOMMIT() asm volatile("cp.async.commit_group;" ::: "memory")
#define CPWAIT0()  asm volatile("cp.async.wait_group 0;" ::: "memory")

// ---------------------------------------------------------------------------
// Kernel 0: convert x and W to single fp16 once
// ---------------------------------------------------------------------------
__global__ __launch_bounds__(256)
void prep_kernel(const float* __restrict__ x, const float* __restrict__ wq,
                 const float* __restrict__ wk, const float* __restrict__ wv)
{
    const int NX4 = TT * DD / 4;   // 786432
    const int NW4 = DD * DD / 4;   // 262144
    int base = blockIdx.x * blockDim.x + threadIdx.x;
    #pragma unroll
    for (int it = 0; it < 2; it++) {
        int idx = base + it * 786432;
        if (idx < NX4) {
            int off = idx * 4;
            float4 v = *(const float4*)(x + off);
            *(uint2*)(g_xh + off) = make_uint2(pkh2(v.x, v.y), pkh2(v.z, v.w));
        } else {
            int j = idx - NX4;
            int w = j / NW4;
            int o = j - w * NW4;
            const float* src = (w == 0) ? wq : ((w == 1) ? wk : wv);
            int off = o * 4;
            float4 v = *(const float4*)(src + off);
            *(uint2*)(g_wh + w * DD * DD + off) =
                make_uint2(pkh2(v.x, v.y), pkh2(v.z, v.w));
        }
    }
}

// ---------------------------------------------------------------------------
// Kernel 1: QKV projection, single fp16, cp.async double-buffered, 2 CTAs/SM.
// Grid (24 n-tiles over [Q|K|V], 24 t-tiles), 256 threads, 128x128 tile.
// Stage: A + B, each 128 rows x 40 u16 (80B stride) = 20480 B
// ---------------------------------------------------------------------------
#define GSTG 20480
#define SMEM_G (2 * GSTG)

__global__ __launch_bounds__(256, 2)
void qkv_mma_kernel(const float* __restrict__ bq, const float* __restrict__ bk,
                    const float* __restrict__ bv)
{
    extern __shared__ char sm[];
    const uint32_t sb = smem_u32(sm);
    const int tid = threadIdx.x;
    const int lane = tid & 31;
    const int wid = tid >> 5;
    const int wm = wid & 1;        // 2 m-tiles of 64
    const int wn = wid >> 1;       // 4 n-tiles of 32
    const int t0 = blockIdx.y * 128;
    const int bn = blockIdx.x;
    const int mat = bn >> 3;
    const int col0 = (bn & 7) << 7;
    const float* bias = (mat == 0) ? bq : ((mat == 1) ? bk : bv);
    const __half* GB = g_wh + mat * DD * DD;

    const int lrow = lane & 15;
    const int lk = (lane >> 4) << 3;

    auto copy_ab = [&](int b, int k0) {
        uint32_t st = sb + b * GSTG;
        #pragma unroll
        for (int i = 0; i < 2; i++) {
            int idx = tid + i * 256;
            int row = idx >> 2;
            int ch = (idx & 3) << 4;      // byte chunk (16 B = 8 fp16)
            int so = row * 80 + ch;
            CP16(st + so,         (const char*)(g_xh + (t0 + row) * DD + k0) + ch);
            CP16(st + 10240 + so, (const char*)(GB + (col0 + row) * DD + k0) + ch);
        }
    };

    float c[4][4][4];
    #pragma unroll
    for (int i = 0; i < 4; i++)
        #pragma unroll
        for (int j = 0; j < 4; j++)
            #pragma unroll
            for (int e = 0; e < 4; e++) c[i][j][e] = 0.f;

    copy_ab(0, 0);
    CPCOMMIT();

    for (int kt = 0; kt < 32; kt++) {
        CPWAIT0();
        __syncthreads();
        if (kt < 31) { copy_ab((kt + 1) & 1, (kt + 1) * 32); CPCOMMIT(); }

        const uint32_t gb = sb + (kt & 1) * GSTG;
        #pragma unroll
        for (int ks = 0; ks < 2; ks++) {
            int kb = ks << 4;
            uint32_t ah[4][4];
            #pragma unroll
            for (int mf = 0; mf < 4; mf++) {
                uint32_t ad = gb + ((wm * 64 + mf * 16 + lrow) * 40 + kb + lk) * 2;
                ldsm4(ah[mf][0], ah[mf][1], ah[mf][2], ah[mf][3], ad);
            }
            uint32_t bh[4][2];
            #pragma unroll
            for (int g = 0; g < 2; g++) {
                uint32_t bd = gb + 10240 +
                    (((wn * 2 + g) * 16 + lrow) * 40 + kb + lk) * 2;
                uint32_t r0, r1, r2, r3;
                ldsm4(r0, r1, r2, r3, bd);
                bh[2 * g][0] = r0; bh[2 * g][1] = r2;
                bh[2 * g + 1][0] = r1; bh[2 * g + 1][1] = r3;
            }
            #pragma unroll
            for (int mf = 0; mf < 4; mf++)
                #pragma unroll
                for (int nf = 0; nf < 4; nf++)
                    mma16816h(c[mf][nf], ah[mf], bh[nf][0], bh[nf][1]);
        }
    }

    // epilogue: bias + permuted scatter (Q scaled by log2e for ex2 softmax)
    const int qr = lane >> 2;
    const int qc = (lane & 3) * 2;
    #pragma unroll
    for (int mf = 0; mf < 4; mf++) {
        #pragma unroll
        for (int rr = 0; rr < 2; rr++) {
            int t = t0 + wm * 64 + mf * 16 + qr + rr * 8;
            int xx = t / 48;
            int toff = t - xx * 48;
            #pragma unroll
            for (int nf = 0; nf < 4; nf++) {
                #pragma unroll
                for (int e = 0; e < 2; e++) {
                    int nn = col0 + wn * 32 + nf * 8 + qc + e;
                    float v = c[mf][nf][rr * 2 + e] + bias[nn];
                    int ee = toff * 1024 + nn;
                    int hh = ee & 15;
                    int ii = ee >> 4;
                    if (mat == 0)
                        g_qh[(hh * TT + ii) * HX + xx] = __float2half_rn(v * LOG2E);
                    else if (mat == 1)
                        g_kh[(hh * TT + ii) * HX + xx] = __float2half_rn(v);
                    else
                        g_vh[(hh * HX + xx) * TT + ii] = __float2half_rn(v);
                }
            }
        }
    }
}

// ---------------------------------------------------------------------------
// Kernel 2: flash attention, 192-row q-tiles, 128 threads (4 warps x 48 rows
// as 3 x 16-row sub-tiles sharing each staged K/V), 2 CTAs/SM, single wave.
// S' = (Q·log2e) K^T;  P = ex2(S' - m');  O += P_fp16 · V_fp16.
// Grid (16 q-tiles, 16 heads).
// smem: Q 27648 | stages 2 x (K 18432 + V 17408) = 99328 B total
// ---------------------------------------------------------------------------
#define AQ   0
#define AST  27648
#define ASTG 35840
#define SMEM_A (27648 + 2 * ASTG)
#define SQK 72    // u16 stride for Q/K rows (144 B)
#define SVT 136   // u16 stride for V^T rows (272 B)

__global__ __launch_bounds__(128, 2)
void attn_mma_kernel(const float* __restrict__ xin,
                     const float* __restrict__ gamma_p,
                     float* __restrict__ out)
{
    extern __shared__ char sm[];
    const uint32_t sb = smem_u32(sm);
    const int tid = threadIdx.x;
    const int lane = tid & 31;
    const int wid = tid >> 5;           // 0..3
    const int h = blockIdx.y;
    const int i0 = blockIdx.x * 192;
    const int lrow = lane & 15;
    const int lk = (lane >> 4) << 3;

    const __half* Qg = g_qh + (h * TT + i0) * HX;
    const __half* Kg = g_kh + h * TT * HX;
    const __half* Vg = g_vh + h * HX * TT;

    auto copy_kv = [&](int b, int j0) {
        uint32_t st = sb + AST + b * ASTG;
        #pragma unroll
        for (int i = 0; i < 8; i++) {
            int idx = tid + i * 128;
            int row = idx >> 3;
            int ch = (idx & 7) << 4;
            CP16(st + row * 144 + ch, (const char*)(Kg + (j0 + row) * HX) + ch);
        }
        #pragma unroll
        for (int i = 0; i < 8; i++) {
            int idx = tid + i * 128;
            int row = idx >> 4;
            int ch = (idx & 15) << 3;       // element chunk (8 halves)
            CP16(st + 18432 + row * 272 + ch * 2, Vg + row * TT + j0 + ch);
        }
    };

    // ---- prefetch Q (192 rows) + KV stage 0 ----
    #pragma unroll
    for (int i = 0; i < 12; i++) {
        int idx = tid + i * 128;
        int row = idx >> 3;
        int ch = (idx & 7) << 4;
        CP16(sb + AQ + row * 144 + ch, (const char*)(Qg + row * HX) + ch);
    }
    copy_kv(0, 0);
    CPCOMMIT();

    float o[3][8][4];
    float mm0[3], mm1[3], ll0[3], ll1[3];
    #pragma unroll
    for (int hf = 0; hf < 3; hf++) {
        mm0[hf] = -1e30f; mm1[hf] = -1e30f; ll0[hf] = 0.f; ll1[hf] = 0.f;
        #pragma unroll
        for (int i = 0; i < 8; i++)
            #pragma unroll
            for (int e = 0; e < 4; e++) o[hf][i][e] = 0.f;
    }

    for (int jt = 0; jt < 24; jt++) {
        CPWAIT0();
        __syncthreads();
        if (jt < 23) { copy_kv((jt + 1) & 1, (jt + 1) * 128); CPCOMMIT(); }

        const uint32_t ST = sb + AST + (jt & 1) * ASTG;
        const uint32_t Kb = ST;
        const uint32_t Vb = ST + 18432;

        #pragma unroll
        for (int hf = 0; hf < 3; hf++) {
            const int qrow = hf * 64 + wid * 16;

            // ---- S = Q K^T for this 16-row sub-tile, all 128 cols ----
            float c[16][4];
            #pragma unroll
            for (int i = 0; i < 16; i++)
                #pragma unroll
                for (int e = 0; e < 4; e++) c[i][e] = 0.f;

            #pragma unroll
            for (int ks = 0; ks < 4; ks++) {
                int kb = ks << 4;
                uint32_t ah[4];
                uint32_t ad = sb + AQ + ((qrow + lrow) * SQK + kb + lk) * 2;
                ldsm4(ah[0], ah[1], ah[2], ah[3], ad);
                #pragma unroll
                for (int ng = 0; ng < 8; ng++) {
                    uint32_t bd = Kb + ((ng * 16 + lrow) * SQK + kb + lk) * 2;
                    uint32_t h0, h1, h2, h3;
                    ldsm4(h0, h1, h2, h3, bd);
                    mma16816h(c[2 * ng],     ah, h0, h2);
                    mma16816h(c[2 * ng + 1], ah, h1, h3);
                }
            }

            // ---- online softmax in log2 domain ----
            float mx0 = -1e30f, mx1 = -1e30f;
            #pragma unroll
            for (int nf = 0; nf < 16; nf++) {
                mx0 = fmaxf(mx0, fmaxf(c[nf][0], c[nf][1]));
                mx1 = fmaxf(mx1, fmaxf(c[nf][2], c[nf][3]));
            }
            mx0 = fmaxf(mx0, __shfl_xor_sync(0xffffffffu, mx0, 1));
            mx0 = fmaxf(mx0, __shfl_xor_sync(0xffffffffu, mx0, 2));
            mx1 = fmaxf(mx1, __shfl_xor_sync(0xffffffffu, mx1, 1));
            mx1 = fmaxf(mx1, __shfl_xor_sync(0xffffffffu, mx1, 2));
            float mn0 = fmaxf(mm0[hf], mx0), mn1 = fmaxf(mm1[hf], mx1);
            float sc0 = ex2(mm0[hf] - mn0), sc1 = ex2(mm1[hf] - mn1);
            float s0 = 0.f, s1 = 0.f;
            #pragma unroll
            for (int nf = 0; nf < 16; nf++) {
                c[nf][0] = ex2(c[nf][0] - mn0); s0 += c[nf][0];
                c[nf][1] = ex2(c[nf][1] - mn0); s0 += c[nf][1];
                c[nf][2] = ex2(c[nf][2] - mn1); s1 += c[nf][2];
                c[nf][3] = ex2(c[nf][3] - mn1); s1 += c[nf][3];
            }
            s0 += __shfl_xor_sync(0xffffffffu, s0, 1);
            s0 += __shfl_xor_sync(0xffffffffu, s0, 2);
            s1 += __shfl_xor_sync(0xffffffffu, s1, 1);
            s1 += __shfl_xor_sync(0xffffffffu, s1, 2);
            ll0[hf] = ll0[hf] * sc0 + s0; mm0[hf] = mn0;
            ll1[hf] = ll1[hf] * sc1 + s1; mm1[hf] = mn1;
            #pragma unroll
            for (int nf = 0; nf < 8; nf++) {
                o[hf][nf][0] *= sc0; o[hf][nf][1] *= sc0;
                o[hf][nf][2] *= sc1; o[hf][nf][3] *= sc1;
            }

            // ---- O += P V ----
            #pragma unroll
            for (int ks2 = 0; ks2 < 8; ks2++) {
                uint32_t ph[4];
                ph[0] = pkh2(c[2 * ks2][0],     c[2 * ks2][1]);
                ph[1] = pkh2(c[2 * ks2][2],     c[2 * ks2][3]);
                ph[2] = pkh2(c[2 * ks2 + 1][0], c[2 * ks2 + 1][1]);
                ph[3] = pkh2(c[2 * ks2 + 1][2], c[2 * ks2 + 1][3]);
                int kb2 = ks2 << 4;
                #pragma unroll
                for (int ng = 0; ng < 4; ng++) {
                    uint32_t bd = Vb + ((ng * 16 + lrow) * SVT + kb2 + lk) * 2;
                    uint32_t h0, h1, h2, h3;
                    ldsm4(h0, h1, h2, h3, bd);
                    mma16816h(o[hf][2 * ng],     ph, h0, h2);
                    mma16816h(o[hf][2 * ng + 1], ph, h1, h3);
                }
            }
        }
    }

    // ---- epilogue: out = gamma * O/l + x (permuted) ----
    const float gma = *gamma_p;
    #pragma unroll
    for (int hf = 0; hf < 3; hf++) {
        const float inv0 = 1.0f / ll0[hf], inv1 = 1.0f / ll1[hf];
        const int r0g = i0 + hf * 64 + wid * 16 + (lane >> 2);
        const int r1g = r0g + 8;
        #pragma unroll
        for (int nf = 0; nf < 8; nf++) {
            #pragma unroll
            for (int e = 0; e < 2; e++) {
                int x = nf * 8 + (lane & 3) * 2 + e;
                int id0 = r0g * DD + x * 16 + h;
                out[id0] = gma * (o[hf][nf][e] * inv0) + xin[id0];
                int id1 = r1g * DD + x * 16 + h;
                out[id1] = gma * (o[hf][nf][2 + e] * inv1) + xin[id1];
            }
        }
    }
}

// ---------------------------------------------------------------------------
extern "C" void kernel_launch(void* const* d_in, const int* in_sizes, int n_in,
                              void* d_out, int out_size)
{
    const float* xin = (const float*)d_in[0];
    const float* wq  = (const float*)d_in[1];
    const float* bq  = (const float*)d_in[2];
    const float* wk  = (const float*)d_in[3];
    const float* bk  = (const float*)d_in[4];
    const float* wv  = (const float*)d_in[5];
    const float* bv  = (const float*)d_in[6];
    const float* gm  = (const float*)d_in[7];
    float* out = (float*)d_out;

    cudaFuncSetAttribute(qkv_mma_kernel,
                         cudaFuncAttributeMaxDynamicSharedMemorySize, SMEM_G);
    cudaFuncSetAttribute(attn_mma_kernel,
                         cudaFuncAttributeMaxDynamicSharedMemorySize, SMEM_A);

    prep_kernel<<<3072, 256>>>(xin, wq, wk, wv);
    qkv_mma_kernel<<<dim3(24, 24), 256, SMEM_G>>>(bq, bk, bv);
    attn_mma_kernel<<<dim3(16, NH), 128, SMEM_A>>>(xin, gm, out);
}

// round 16
// speedup vs baseline: 1.3656x; 1.3656x over previous
#include <cuda_runtime.h>
#include <cuda_fp16.h>
#include <cstdint>

#define TT 3072
#define DD 1024
#define NH 16
#define HX 64
#define LOG2E 1.4426950408889634f

// ---------------------------------------------------------------------------
// Global scratch (all single fp16).  Q is pre-scaled by log2(e).
// ---------------------------------------------------------------------------
__device__ __align__(16) __half g_xh[TT * DD];                    // x
__device__ __align__(16) __half g_wh[3 * DD * DD];                // W
__device__ __align__(16) __half g_qh[TT * DD];                    // [h][t][x] (x log2e)
__device__ __align__(16) __half g_kh[TT * DD];                    // [h][j][x]
__device__ __align__(16) __half g_vh[TT * DD];                    // [h][x][j]

// ---------------------------------------------------------------------------
// helpers
// ---------------------------------------------------------------------------
__device__ __forceinline__ uint32_t smem_u32(const void* p) {
    uint32_t a;
    asm("{ .reg .u64 t; cvta.to.shared.u64 t, %1; cvt.u32.u64 %0, t; }"
        : "=r"(a) : "l"(p));
    return a;
}
__device__ __forceinline__ void ldsm4(uint32_t& r0, uint32_t& r1,
                                      uint32_t& r2, uint32_t& r3, uint32_t a) {
    asm volatile("ldmatrix.sync.aligned.m8n8.x4.shared.b16 {%0,%1,%2,%3}, [%4];"
                 : "=r"(r0), "=r"(r1), "=r"(r2), "=r"(r3) : "r"(a));
}
__device__ __forceinline__ void mma16816h(float* c, const uint32_t* a,
                                          uint32_t b0, uint32_t b1) {
    asm volatile("mma.sync.aligned.m16n8k16.row.col.f32.f16.f16.f32 "
                 "{%0,%1,%2,%3}, {%4,%5,%6,%7}, {%8,%9}, {%0,%1,%2,%3};"
                 : "+f"(c[0]), "+f"(c[1]), "+f"(c[2]), "+f"(c[3])
                 : "r"(a[0]), "r"(a[1]), "r"(a[2]), "r"(a[3]), "r"(b0), "r"(b1));
}
__device__ __forceinline__ uint32_t pkh2(float a, float b) {
    __half2 t = __floats2half2_rn(a, b);
    return *(uint32_t*)&t;
}
__device__ __forceinline__ float ex2(float x) {
    float r;
    asm("ex2.approx.ftz.f32 %0, %1;" : "=f"(r) : "f"(x));
    return r;
}

#define CP16(dst, src) \
    asm volatile("cp.async.cg.shared.global [%0], [%1], 16;" \
                 :: "r"((uint32_t)(dst)), "l"((const void*)(src)) : "memory")
#define CPCOMMIT() asm volatile("cp.async.commit_group;" ::: "memory")
#define CPWAIT0()  asm volatile("cp.async.wait_group 0;" ::: "memory")

// ---------------------------------------------------------------------------
// Kernel 0: convert x and W to single fp16 once
// ---------------------------------------------------------------------------
__global__ __launch_bounds__(256)
void prep_kernel(const float* __restrict__ x, const float* __restrict__ wq,
                 const float* __restrict__ wk, const float* __restrict__ wv)
{
    const int NX4 = TT * DD / 4;   // 786432
    const int NW4 = DD * DD / 4;   // 262144
    int base = blockIdx.x * blockDim.x + threadIdx.x;
    #pragma unroll
    for (int it = 0; it < 2; it++) {
        int idx = base + it * 786432;
        if (idx < NX4) {
            int off = idx * 4;
            float4 v = *(const float4*)(x + off);
            *(uint2*)(g_xh + off) = make_uint2(pkh2(v.x, v.y), pkh2(v.z, v.w));
        } else {
            int j = idx - NX4;
            int w = j / NW4;
            int o = j - w * NW4;
            const float* src = (w == 0) ? wq : ((w == 1) ? wk : wv);
            int off = o * 4;
            float4 v = *(const float4*)(src + off);
            *(uint2*)(g_wh + w * DD * DD + off) =
                make_uint2(pkh2(v.x, v.y), pkh2(v.z, v.w));
        }
    }
}

// ---------------------------------------------------------------------------
// Kernel 1: QKV projection, single fp16, cp.async double-buffered, 2 CTAs/SM.
// Grid (24 n-tiles over [Q|K|V], 24 t-tiles), 256 threads, 128x128 tile.
// Stage: A + B, each 128 rows x 40 u16 (80B stride) = 20480 B
// ---------------------------------------------------------------------------
#define GSTG 20480
#define SMEM_G (2 * GSTG)

__global__ __launch_bounds__(256, 2)
void qkv_mma_kernel(const float* __restrict__ bq, const float* __restrict__ bk,
                    const float* __restrict__ bv)
{
    extern __shared__ char sm[];
    const uint32_t sb = smem_u32(sm);
    const int tid = threadIdx.x;
    const int lane = tid & 31;
    const int wid = tid >> 5;
    const int wm = wid & 1;        // 2 m-tiles of 64
    const int wn = wid >> 1;       // 4 n-tiles of 32
    const int t0 = blockIdx.y * 128;
    const int bn = blockIdx.x;
    const int mat = bn >> 3;
    const int col0 = (bn & 7) << 7;
    const float* bias = (mat == 0) ? bq : ((mat == 1) ? bk : bv);
    const __half* GB = g_wh + mat * DD * DD;

    const int lrow = lane & 15;
    const int lk = (lane >> 4) << 3;

    auto copy_ab = [&](int b, int k0) {
        uint32_t st = sb + b * GSTG;
        #pragma unroll
        for (int i = 0; i < 2; i++) {
            int idx = tid + i * 256;
            int row = idx >> 2;
            int ch = (idx & 3) << 4;      // byte chunk (16 B = 8 fp16)
            int so = row * 80 + ch;
            CP16(st + so,         (const char*)(g_xh + (t0 + row) * DD + k0) + ch);
            CP16(st + 10240 + so, (const char*)(GB + (col0 + row) * DD + k0) + ch);
        }
    };

    float c[4][4][4];
    #pragma unroll
    for (int i = 0; i < 4; i++)
        #pragma unroll
        for (int j = 0; j < 4; j++)
            #pragma unroll
            for (int e = 0; e < 4; e++) c[i][j][e] = 0.f;

    copy_ab(0, 0);
    CPCOMMIT();

    for (int kt = 0; kt < 32; kt++) {
        CPWAIT0();
        __syncthreads();
        if (kt < 31) { copy_ab((kt + 1) & 1, (kt + 1) * 32); CPCOMMIT(); }

        const uint32_t gb = sb + (kt & 1) * GSTG;
        #pragma unroll
        for (int ks = 0; ks < 2; ks++) {
            int kb = ks << 4;
            uint32_t ah[4][4];
            #pragma unroll
            for (int mf = 0; mf < 4; mf++) {
                uint32_t ad = gb + ((wm * 64 + mf * 16 + lrow) * 40 + kb + lk) * 2;
                ldsm4(ah[mf][0], ah[mf][1], ah[mf][2], ah[mf][3], ad);
            }
            uint32_t bh[4][2];
            #pragma unroll
            for (int g = 0; g < 2; g++) {
                uint32_t bd = gb + 10240 +
                    (((wn * 2 + g) * 16 + lrow) * 40 + kb + lk) * 2;
                uint32_t r0, r1, r2, r3;
                ldsm4(r0, r1, r2, r3, bd);
                bh[2 * g][0] = r0; bh[2 * g][1] = r2;
                bh[2 * g + 1][0] = r1; bh[2 * g + 1][1] = r3;
            }
            #pragma unroll
            for (int mf = 0; mf < 4; mf++)
                #pragma unroll
                for (int nf = 0; nf < 4; nf++)
                    mma16816h(c[mf][nf], ah[mf], bh[nf][0], bh[nf][1]);
        }
    }

    // epilogue: bias + permuted scatter (Q scaled by log2e for ex2 softmax)
    const int qr = lane >> 2;
    const int qc = (lane & 3) * 2;
    #pragma unroll
    for (int mf = 0; mf < 4; mf++) {
        #pragma unroll
        for (int rr = 0; rr < 2; rr++) {
            int t = t0 + wm * 64 + mf * 16 + qr + rr * 8;
            int xx = t / 48;
            int toff = t - xx * 48;
            #pragma unroll
            for (int nf = 0; nf < 4; nf++) {
                #pragma unroll
                for (int e = 0; e < 2; e++) {
                    int nn = col0 + wn * 32 + nf * 8 + qc + e;
                    float v = c[mf][nf][rr * 2 + e] + bias[nn];
                    int ee = toff * 1024 + nn;
                    int hh = ee & 15;
                    int ii = ee >> 4;
                    if (mat == 0)
                        g_qh[(hh * TT + ii) * HX + xx] = __float2half_rn(v * LOG2E);
                    else if (mat == 1)
                        g_kh[(hh * TT + ii) * HX + xx] = __float2half_rn(v);
                    else
                        g_vh[(hh * HX + xx) * TT + ii] = __float2half_rn(v);
                }
            }
        }
    }
}

// ---------------------------------------------------------------------------
// Kernel 2: flash attention, 64-row q-tiles, 128 threads, 2 CTAs/SM.
// S' = (Q·log2e) K^T;  P = ex2(S' - m') fused INTO the PV loop so MUFU/ALU
// issue overlaps tensor-pipe PV MMAs.  O += P_fp16 · V_fp16.
// Grid (48 q-tiles, 16 heads), 4 warps x 16 query rows.
// smem: Q 9216 | stages 2 x (K 18432 + V 17408) = 80896 B total
// ---------------------------------------------------------------------------
#define AQ   0
#define AST  9216
#define ASTG 35840
#define SMEM_A (9216 + 2 * ASTG)
#define SQK 72    // u16 stride for Q/K rows (144 B)
#define SVT 136   // u16 stride for V^T rows (272 B)

__global__ __launch_bounds__(128, 2)
void attn_mma_kernel(const float* __restrict__ xin,
                     const float* __restrict__ gamma_p,
                     float* __restrict__ out)
{
    extern __shared__ char sm[];
    const uint32_t sb = smem_u32(sm);
    const int tid = threadIdx.x;
    const int lane = tid & 31;
    const int wid = tid >> 5;           // 0..3
    const int h = blockIdx.y;
    const int i0 = blockIdx.x * 64;
    const int lrow = lane & 15;
    const int lk = (lane >> 4) << 3;

    const __half* Qg = g_qh + (h * TT + i0) * HX;
    const __half* Kg = g_kh + h * TT * HX;
    const __half* Vg = g_vh + h * HX * TT;

    auto copy_kv = [&](int b, int j0) {
        uint32_t st = sb + AST + b * ASTG;
        #pragma unroll
        for (int i = 0; i < 8; i++) {
            int idx = tid + i * 128;
            int row = idx >> 3;
            int ch = (idx & 7) << 4;
            CP16(st + row * 144 + ch, (const char*)(Kg + (j0 + row) * HX) + ch);
        }
        #pragma unroll
        for (int i = 0; i < 8; i++) {
            int idx = tid + i * 128;
            int row = idx >> 4;
            int ch = (idx & 15) << 3;       // element chunk (8 halves)
            CP16(st + 18432 + row * 272 + ch * 2, Vg + row * TT + j0 + ch);
        }
    };

    // ---- prefetch Q (64 rows) + KV stage 0 ----
    #pragma unroll
    for (int i = 0; i < 4; i++) {
        int idx = tid + i * 128;
        int row = idx >> 3;
        int ch = (idx & 7) << 4;
        CP16(sb + AQ + row * 144 + ch, (const char*)(Qg + row * HX) + ch);
    }
    copy_kv(0, 0);
    CPCOMMIT();

    float o[8][4];
    #pragma unroll
    for (int i = 0; i < 8; i++)
        #pragma unroll
        for (int e = 0; e < 4; e++) o[i][e] = 0.f;
    float m0 = -1e30f, m1 = -1e30f, l0 = 0.f, l1 = 0.f;

    for (int jt = 0; jt < 24; jt++) {
        CPWAIT0();
        __syncthreads();
        if (jt < 23) { copy_kv((jt + 1) & 1, (jt + 1) * 128); CPCOMMIT(); }

        const uint32_t ST = sb + AST + (jt & 1) * ASTG;
        const uint32_t Kb = ST;
        const uint32_t Vb = ST + 18432;

        // ---- S = Q K^T : warp rows [wid*16, wid*16+16), all 128 cols ----
        float c[16][4];
        #pragma unroll
        for (int i = 0; i < 16; i++)
            #pragma unroll
            for (int e = 0; e < 4; e++) c[i][e] = 0.f;

        #pragma unroll
        for (int ks = 0; ks < 4; ks++) {
            int kb = ks << 4;
            uint32_t ah[4];
            uint32_t ad = sb + AQ + ((wid * 16 + lrow) * SQK + kb + lk) * 2;
            ldsm4(ah[0], ah[1], ah[2], ah[3], ad);
            #pragma unroll
            for (int ng = 0; ng < 8; ng++) {
                uint32_t bd = Kb + ((ng * 16 + lrow) * SQK + kb + lk) * 2;
                uint32_t h0, h1, h2, h3;
                ldsm4(h0, h1, h2, h3, bd);
                mma16816h(c[2 * ng],     ah, h0, h2);
                mma16816h(c[2 * ng + 1], ah, h1, h3);
            }
        }

        // ---- row max (log2 domain) ----
        float mx0 = -1e30f, mx1 = -1e30f;
        #pragma unroll
        for (int nf = 0; nf < 16; nf++) {
            mx0 = fmaxf(mx0, fmaxf(c[nf][0], c[nf][1]));
            mx1 = fmaxf(mx1, fmaxf(c[nf][2], c[nf][3]));
        }
        mx0 = fmaxf(mx0, __shfl_xor_sync(0xffffffffu, mx0, 1));
        mx0 = fmaxf(mx0, __shfl_xor_sync(0xffffffffu, mx0, 2));
        mx1 = fmaxf(mx1, __shfl_xor_sync(0xffffffffu, mx1, 1));
        mx1 = fmaxf(mx1, __shfl_xor_sync(0xffffffffu, mx1, 2));
        float mn0 = fmaxf(m0, mx0), mn1 = fmaxf(m1, mx1);
        float sc0 = ex2(m0 - mn0), sc1 = ex2(m1 - mn1);
        m0 = mn0; m1 = mn1;
        #pragma unroll
        for (int nf = 0; nf < 8; nf++) {
            o[nf][0] *= sc0; o[nf][1] *= sc0;
            o[nf][2] *= sc1; o[nf][3] *= sc1;
        }

        // ---- fused: per-chunk exp + sum + pack + PV MMA (MUFU hides
        //      under tensor work of the previous chunk) ----
        float s0 = 0.f, s1 = 0.f;
        #pragma unroll
        for (int ks2 = 0; ks2 < 8; ks2++) {
            float p00 = ex2(c[2 * ks2][0] - mn0);
            float p01 = ex2(c[2 * ks2][1] - mn0);
            float p02 = ex2(c[2 * ks2][2] - mn1);
            float p03 = ex2(c[2 * ks2][3] - mn1);
            float p10 = ex2(c[2 * ks2 + 1][0] - mn0);
            float p11 = ex2(c[2 * ks2 + 1][1] - mn0);
            float p12 = ex2(c[2 * ks2 + 1][2] - mn1);
            float p13 = ex2(c[2 * ks2 + 1][3] - mn1);
            s0 += (p00 + p01) + (p10 + p11);
            s1 += (p02 + p03) + (p12 + p13);
            uint32_t ph[4];
            ph[0] = pkh2(p00, p01);
            ph[1] = pkh2(p02, p03);
            ph[2] = pkh2(p10, p11);
            ph[3] = pkh2(p12, p13);
            int kb2 = ks2 << 4;
            #pragma unroll
            for (int ng = 0; ng < 4; ng++) {
                uint32_t bd = Vb + ((ng * 16 + lrow) * SVT + kb2 + lk) * 2;
                uint32_t h0, h1, h2, h3;
                ldsm4(h0, h1, h2, h3, bd);
                mma16816h(o[2 * ng],     ph, h0, h2);
                mma16816h(o[2 * ng + 1], ph, h1, h3);
            }
        }
        s0 += __shfl_xor_sync(0xffffffffu, s0, 1);
        s0 += __shfl_xor_sync(0xffffffffu, s0, 2);
        s1 += __shfl_xor_sync(0xffffffffu, s1, 1);
        s1 += __shfl_xor_sync(0xffffffffu, s1, 2);
        l0 = l0 * sc0 + s0;
        l1 = l1 * sc1 + s1;
    }

    // ---- epilogue: out = gamma * O/l + x (permuted) ----
    const float gma = *gamma_p;
    const float inv0 = 1.0f / l0, inv1 = 1.0f / l1;
    const int r0g = i0 + wid * 16 + (lane >> 2);
    const int r1g = r0g + 8;
    #pragma unroll
    for (int nf = 0; nf < 8; nf++) {
        #pragma unroll
        for (int e = 0; e < 2; e++) {
            int x = nf * 8 + (lane & 3) * 2 + e;
            int id0 = r0g * DD + x * 16 + h;
            out[id0] = gma * (o[nf][e] * inv0) + xin[id0];
            int id1 = r1g * DD + x * 16 + h;
            out[id1] = gma * (o[nf][2 + e] * inv1) + xin[id1];
        }
    }
}

// ---------------------------------------------------------------------------
extern "C" void kernel_launch(void* const* d_in, const int* in_sizes, int n_in,
                              void* d_out, int out_size)
{
    const float* xin = (const float*)d_in[0];
    const float* wq  = (const float*)d_in[1];
    const float* bq  = (const float*)d_in[2];
    const float* wk  = (const float*)d_in[3];
    const float* bk  = (const float*)d_in[4];
    const float* wv  = (const float*)d_in[5];
    const float* bv  = (const float*)d_in[6];
    const float* gm  = (const float*)d_in[7];
    float* out = (float*)d_out;

    cudaFuncSetAttribute(qkv_mma_kernel,
                         cudaFuncAttributeMaxDynamicSharedMemorySize, SMEM_G);
    cudaFuncSetAttribute(attn_mma_kernel,
                         cudaFuncAttributeMaxDynamicSharedMemorySize, SMEM_A);

    prep_kernel<<<3072, 256>>>(xin, wq, wk, wv);
    qkv_mma_kernel<<<dim3(24, 24), 256, SMEM_G>>>(bq, bk, bv);
    attn_mma_kernel<<<dim3(48, NH), 128, SMEM_A>>>(xin, gm, out);
}